// round 13
// baseline (speedup 1.0000x reference)
#include <cuda_runtime.h>
#include <cuda_bf16.h>

// Problem constants: A is (B, N, T) float32
#define B_DIM 64
#define N_DIM 512
#define T_DIM 2048
#define CHUNK 8                      // rows (n) per work item
#define THREADS 256
#define ITEMS_PER_B (N_DIM / CHUNK)  // 64
#define TOTAL_ITEMS (B_DIM * ITEMS_PER_B)  // 4096
#define GRID_BLOCKS 1216             // 152 SMs x 8 CTAs: exactly one wave

// Device globals; finalize path resets them each call so graph replays start clean.
__device__ double g_acc;
__device__ unsigned int g_count;
__device__ unsigned int g_ticket = GRID_BLOCKS;  // first GRID_BLOCKS items are static

__global__ __launch_bounds__(THREADS) void gal_fused_kernel(
    const float* __restrict__ A,
    const float* __restrict__ g_ptr,
    const int*   __restrict__ mel_lens,
    const int*   __restrict__ seq_lens,
    float*       __restrict__ out)
{
    float acc_e = 0.0f;   // sum of e * a
    float acc_a = 0.0f;   // sum of a   (contribution = acc_a - acc_e)

    const float g = g_ptr[0];
    const float inv2g2 = 1.0f / (2.0f * g * g);
    const float s_const = sqrtf(1.44269504088896f * inv2g2); // u = diff*s -> e=2^(-u^2)

    __shared__ unsigned s_next;
    unsigned cur = blockIdx.x;   // static first item

    while (cur < TOTAL_ITEMS) {
        // fetch next ticket early; latency overlaps item processing
        if (threadIdx.x == 0) s_next = atomicAdd(&g_ticket, 1u);

        const int b  = (int)(cur & (B_DIM - 1));
        const int n0 = (int)(cur >> 6) * CHUNK;     // cur / B_DIM * CHUNK
        const int seq_len = seq_lens[b];

        if (n0 < seq_len) {
            const int mel_len = mel_lens[b];
            const float inv_seq = 1.0f / (float)seq_len;
            const float inv_mel = 1.0f / (float)mel_len;
            const float se   = inv_mel * s_const;          // u step per t element
            const float srow = inv_seq * s_const;          // u step per n row
            const float sg1  = (float)(THREADS * 4) * se;  // offset to 2nd group

            const int nrows = min(CHUNK, seq_len - n0);
            const int nfull = mel_len >> 2;   // fully-live float4 groups (>=256)
            const int rem   = mel_len & 3;

            const int v0 = threadIdx.x;       // group 0 (always < nfull)
            const int v1 = v0 + THREADS;      // group 1
            const bool p1 = v1 < nfull;
            const bool own_part = (rem != 0) && ((nfull & (THREADS - 1)) == v0)
                                  && (nfull < (T_DIM >> 2));

            float un = (float)n0 * srow - (float)(v0 << 2) * se;

            const float4* rp = reinterpret_cast<const float4*>(
                A + ((size_t)b * N_DIM + (size_t)n0) * T_DIM);
            const int rstride = T_DIM / 4;

#define GAL_G(AA, UG) do {                                               \
            float u0 = (UG);                                             \
            float u1 = u0 - se;                                          \
            float u2 = u1 - se;                                          \
            float u3 = u2 - se;                                          \
            float e0, e1, e2, e3;                                        \
            asm("ex2.approx.ftz.f32 %0, %1;" : "=f"(e0) : "f"(-u0 * u0));\
            asm("ex2.approx.ftz.f32 %0, %1;" : "=f"(e1) : "f"(-u1 * u1));\
            asm("ex2.approx.ftz.f32 %0, %1;" : "=f"(e2) : "f"(-u2 * u2));\
            asm("ex2.approx.ftz.f32 %0, %1;" : "=f"(e3) : "f"(-u3 * u3));\
            acc_e = fmaf(e0, (AA).x, acc_e);                             \
            acc_e = fmaf(e1, (AA).y, acc_e);                             \
            acc_e = fmaf(e2, (AA).z, acc_e);                             \
            acc_e = fmaf(e3, (AA).w, acc_e);                             \
            acc_a += ((AA).x + (AA).y) + ((AA).z + (AA).w);              \
} while (0)

#define GAL_ROW(X0, X1, RP, UN) do {                                     \
            GAL_G(X0, (UN));                                             \
            if (p1) GAL_G(X1, (UN) - sg1);                               \
            if (own_part) {                                              \
                const float4 ap = __ldcs((RP) + nfull);                  \
                float u = (UN) - (float)((nfull - v0) << 2) * se;        \
                float e;                                                 \
                asm("ex2.approx.ftz.f32 %0, %1;" : "=f"(e) : "f"(-u * u));\
                acc_e = fmaf(e, ap.x, acc_e); acc_a += ap.x;             \
                if (rem > 1) { u -= se;                                  \
                    asm("ex2.approx.ftz.f32 %0, %1;" : "=f"(e) : "f"(-u * u)); \
                    acc_e = fmaf(e, ap.y, acc_e); acc_a += ap.y; }       \
                if (rem > 2) { u -= se;                                  \
                    asm("ex2.approx.ftz.f32 %0, %1;" : "=f"(e) : "f"(-u * u)); \
                    acc_e = fmaf(e, ap.z, acc_e); acc_a += ap.z; }       \
            }                                                            \
} while (0)

            float4 a0, a1, b0, b1;
            a0 = __ldcs(rp + v0);
            if (p1) a1 = __ldcs(rp + v1);

            int r = 0;
            for (; r + 2 <= nrows; r += 2) {
                const float4* rp1 = rp + rstride;
                b0 = __ldcs(rp1 + v0);
                if (p1) b1 = __ldcs(rp1 + v1);

                GAL_ROW(a0, a1, rp, un);
                un += srow;

                const float4* rp2 = rp1 + rstride;
                if (r + 2 < nrows) {
                    a0 = __ldcs(rp2 + v0);
                    if (p1) a1 = __ldcs(rp2 + v1);
                }

                GAL_ROW(b0, b1, rp1, un);
                un += srow;
                rp = rp2;
            }
            if (r < nrows) {
                GAL_ROW(a0, a1, rp, un);
            }
#undef GAL_ROW
#undef GAL_G
        }

        __syncthreads();        // s_next written and everyone done with item
        cur = s_next;
        __syncthreads();        // all have read s_next before next overwrite
    }

    // block reduce; every block participates so the ticket count is exact
    float acc = acc_a - acc_e;
    #pragma unroll
    for (int off = 16; off > 0; off >>= 1)
        acc += __shfl_down_sync(0xffffffffu, acc, off);

    __shared__ float warp_sums[THREADS / 32];
    const int lane = threadIdx.x & 31;
    const int wid  = threadIdx.x >> 5;
    if (lane == 0) warp_sums[wid] = acc;
    __syncthreads();

    if (threadIdx.x == 0) {
        double ssum = 0.0;
        #pragma unroll
        for (int i = 0; i < THREADS / 32; i++) ssum += (double)warp_sums[i];
        atomicAdd(&g_acc, ssum);
        __threadfence();
        unsigned t = atomicAdd(&g_count, 1u);
        if (t == (unsigned)gridDim.x - 1) {
            // all blocks have finished fetching tickets and accumulating
            double tot = atomicAdd(&g_acc, 0.0);
            out[0] = (float)(tot / (double)B_DIM);
            g_acc    = 0.0;
            g_count  = 0u;
            g_ticket = GRID_BLOCKS;   // rearm for next graph replay
        }
    }
}

extern "C" void kernel_launch(void* const* d_in, const int* in_sizes, int n_in,
                              void* d_out, int out_size) {
    const float* A        = (const float*)d_in[0];
    const float* g_ptr    = (const float*)d_in[1];
    const int*   mel_lens = (const int*)d_in[2];
    const int*   seq_lens = (const int*)d_in[3];
    float*       out      = (float*)d_out;

    gal_fused_kernel<<<GRID_BLOCKS, THREADS>>>(A, g_ptr, mel_lens, seq_lens, out);
}